// round 16
// baseline (speedup 1.0000x reference)
#include <cuda_runtime.h>
#include <cuda_fp16.h>
#include <stdint.h>

// Problem dims (fixed by the dataset)
#define FDIM 16384   // n_features
#define DDIM 768     // d_model
#define NB   1024    // B*S
#define MCONN 262144 // n_connections

// -------- scratch (device globals; no allocation allowed) --------
__device__ __half g_udTh[(size_t)FDIM * DDIM]; // up_decoder^T fp16: [F, D] (~25 MB)
__device__ __half g_XTh[(size_t)FDIM * NB];    // up_facts^T fp16:   [F, NB] (~33 MB)
__device__ int    g_joff[MCONN];               // xt byte offset = j*2048
__device__ int    g_rowstart[FDIM + 1];        // CSR offsets over sorted i

// ---------------------------------------------------------------
// Inline int64-vs-int32 detection on the i_indices buffer (values
// < 16384 => odd int32-words of an int64 array are all zero; for
// int32 data the probed words are sorted indices ~8192 != 0).
// ---------------------------------------------------------------
__device__ __forceinline__ int detect_is64(const int* raw) {
    int q = MCONN / 4;
    int nz = 0;
#pragma unroll
    for (int k = 0; k < 8; k++) nz |= raw[2 * (q + k) + 1];
    return nz ? 0 : 1;
}

__device__ __forceinline__ int idx_at(const void* p, int is64, int m) {
    return is64 ? (int)((const long long*)p)[m] : ((const int*)p)[m];
}

// ================================================================
// K1: fused prep = transpose_ud | transpose_x | csr_scatter | jconv
// Transpose: 32(r) x 128(f) tiles, float4 loads, pad-1 smem
// (conflict-free both phases), uint2 (4-half) stores.
// ================================================================
#define K1_UD   3072                  // 128 F-tiles * 24 D-tiles
#define K1_XT   (K1_UD + 4096)       // + 128 F-tiles * 32 NB-tiles
#define K1_CSR  (K1_XT + 1024)
#define K1_TOT  (K1_CSR + 1024)

__global__ __launch_bounds__(256) void k1_prep(const float* __restrict__ up_dec,
                                               const float* __restrict__ up_facts,
                                               const void* __restrict__ ii,
                                               const void* __restrict__ jj) {
    int b = blockIdx.x;
    if (b < K1_XT) {
        __shared__ float tile[32 * 129];   // [r][f], row stride 129
        const float* src;
        __half* dst;
        int c0, r0, ostride;
        if (b < K1_UD) {
            int fblk = b & 127, rblk = b >> 7;
            c0 = fblk * 128; r0 = rblk * 32;
            src = up_dec; dst = g_udTh; ostride = DDIM;
        } else {
            int b2 = b - K1_UD;
            int fblk = b2 & 127, rblk = b2 >> 7;
            c0 = fblk * 128; r0 = rblk * 32;
            src = up_facts; dst = g_XTh; ostride = NB;
        }
        // load: 32 rows x 32 float4; 4 float4 per thread
        int r  = threadIdx.x >> 3;
        int cb = threadIdx.x & 7;
        const float4* srow = (const float4*)(src + (size_t)(r0 + r) * FDIM + c0);
        float* trow = &tile[r * 129];
#pragma unroll
        for (int k = 0; k < 4; k++) {
            int c = cb + 8 * k;
            float4 v = __ldcs(&srow[c]);
            trow[4 * c + 0] = v.x;
            trow[4 * c + 1] = v.y;
            trow[4 * c + 2] = v.z;
            trow[4 * c + 3] = v.w;
        }
        __syncthreads();
        // store: 128 fy x 8 r-quads; 4 uint2 per thread
#pragma unroll
        for (int k = 0; k < 4; k++) {
            int task = threadIdx.x + 256 * k;
            int fy = task >> 3;
            int rq = task & 7;
            float f0 = tile[(4 * rq + 0) * 129 + fy];
            float f1 = tile[(4 * rq + 1) * 129 + fy];
            float f2 = tile[(4 * rq + 2) * 129 + fy];
            float f3 = tile[(4 * rq + 3) * 129 + fy];
            __half2 h0 = __floats2half2_rn(f0, f1);
            __half2 h1 = __floats2half2_rn(f2, f3);
            uint2 o;
            o.x = *(const unsigned*)&h0;
            o.y = *(const unsigned*)&h1;
            *(uint2*)&dst[(size_t)(c0 + fy) * ostride + r0 + 4 * rq] = o;
        }
    } else if (b < K1_CSR) {
        int m = (b - K1_XT) * 256 + threadIdx.x;
        int is64 = detect_is64((const int*)ii);
        int cur = idx_at(ii, is64, m);
        int prev = (m == 0) ? -1 : idx_at(ii, is64, m - 1);
        for (int i = prev + 1; i <= cur; i++) g_rowstart[i] = m;
        if (m == MCONN - 1)
            for (int i = cur + 1; i <= FDIM; i++) g_rowstart[i] = MCONN;
    } else {
        int m = (b - K1_CSR) * 256 + threadIdx.x;
        int is64 = detect_is64((const int*)ii);
        g_joff[m] = idx_at(jj, is64, m) << 11;   // j * NB * sizeof(half)
    }
}

// ================================================================
// K2: fused values + SpMM per i-tile.
//   Phase V: warp w computes values for row i0+w (de row in regs,
//            batch-2 fp16 dots vs udT) -> se[].y in smem.
//   Phase S: all threads run the SpMM over the tile (8 n/thread,
//            16B gathers from XT, 8-wide MLP batches).
// ================================================================
#define ITILE 4
#define NTHR  128
#define CHUNK 256

__device__ __forceinline__ float dot24p(const float a[3][8],
                                        uint4 b0, uint4 b1, uint4 b2) {
    float sum = 0.f;
    uint4 bs[3] = {b0, b1, b2};
#pragma unroll
    for (int k = 0; k < 3; k++) {
        const __half2* h = (const __half2*)&bs[k];
#pragma unroll
        for (int t = 0; t < 4; t++) {
            float2 f = __half22float2(h[t]);
            sum += a[k][2 * t] * f.x + a[k][2 * t + 1] * f.y;
        }
    }
    return sum;
}

__device__ __forceinline__ void fma8(float acc[8], float v, uint4 u) {
    const __half2* h = (const __half2*)&u;
#pragma unroll
    for (int t = 0; t < 4; t++) {
        float2 f = __half22float2(h[t]);
        acc[2 * t]     += v * f.x;
        acc[2 * t + 1] += v * f.y;
    }
}

__global__ __launch_bounds__(NTHR) void k2_fused(const float* __restrict__ de,
                                                 float* __restrict__ out) {
    __shared__ int2 se[CHUNK];          // {xt byte offset, value bits}
    __shared__ int  soff[ITILE + 1];

    int i0   = blockIdx.x * ITILE;
    int wid  = threadIdx.x >> 5;        // 0..3 == row within tile
    int lane = threadIdx.x & 31;
    int n0   = threadIdx.x * 8;

    if (threadIdx.x <= ITILE) soff[threadIdx.x] = g_rowstart[i0 + threadIdx.x];
    __syncthreads();

    int mbase = soff[0];
    int mend  = soff[ITILE];
    int rs_w  = soff[wid];              // this warp's row range (phase V)
    int re_w  = soff[wid + 1];

    // Cache de[i0+wid,:] lane slice: elements 8*(2*lane+64k) .. +7, k<3
    float a[3][8];
    {
        const float4* dev = (const float4*)(de + (size_t)(i0 + wid) * DDIM);
#pragma unroll
        for (int k = 0; k < 3; k++) {
            float4 p = dev[2 * lane + 64 * k];
            float4 q = dev[2 * lane + 64 * k + 1];
            a[k][0] = p.x; a[k][1] = p.y; a[k][2] = p.z; a[k][3] = p.w;
            a[k][4] = q.x; a[k][5] = q.y; a[k][6] = q.z; a[k][7] = q.w;
        }
    }

    const char* xbase = (const char*)g_XTh + n0 * 2;

    float acc[ITILE][8];
#pragma unroll
    for (int k = 0; k < ITILE; k++)
#pragma unroll
        for (int r = 0; r < 8; r++) acc[k][r] = 0.f;

    for (int cb = mbase; cb < mend; cb += CHUNK) {
        int cend = min(cb + CHUNK, mend);
        __syncthreads();                               // guard se reuse
        for (int t = threadIdx.x; cb + t < cend; t += NTHR)
            se[t].x = g_joff[cb + t];
        __syncthreads();

        // ---- Phase V: values for this warp's row within [cb, cend) ----
        {
            int ms = max(rs_w, cb);
            int me = min(re_w, cend);
            int m = ms;
            for (; m + 2 <= me; m += 2) {
                int j0 = se[m - cb].x >> 11;
                int j1 = se[m + 1 - cb].x >> 11;
                const uint4* u0 = (const uint4*)(g_udTh + (size_t)j0 * DDIM);
                const uint4* u1 = (const uint4*)(g_udTh + (size_t)j1 * DDIM);
                uint4 b00 = u0[lane], b01 = u0[lane + 32], b02 = u0[lane + 64];
                uint4 b10 = u1[lane], b11 = u1[lane + 32], b12 = u1[lane + 64];
                float s0 = dot24p(a, b00, b01, b02);
                float s1 = dot24p(a, b10, b11, b12);
#pragma unroll
                for (int o = 16; o; o >>= 1) {
                    s0 += __shfl_xor_sync(0xffffffffu, s0, o);
                    s1 += __shfl_xor_sync(0xffffffffu, s1, o);
                }
                if (lane == 0) {
                    se[m - cb].y     = __float_as_int(s0);
                    se[m + 1 - cb].y = __float_as_int(s1);
                }
            }
            if (m < me) {
                int j0 = se[m - cb].x >> 11;
                const uint4* u0 = (const uint4*)(g_udTh + (size_t)j0 * DDIM);
                float s0 = dot24p(a, u0[lane], u0[lane + 32], u0[lane + 64]);
#pragma unroll
                for (int o = 16; o; o >>= 1) s0 += __shfl_xor_sync(0xffffffffu, s0, o);
                if (lane == 0) se[m - cb].y = __float_as_int(s0);
            }
        }
        __syncthreads();

        // ---- Phase S: SpMM over the tile ----
#pragma unroll
        for (int il = 0; il < ITILE; il++) {
            int ms = max(soff[il], cb) - cb;
            int me = min(soff[il + 1], cend) - cb;
            int m = ms;
            for (; m + 8 <= me; m += 8) {
                int2 e0 = se[m],     e1 = se[m + 1], e2 = se[m + 2], e3 = se[m + 3];
                int2 e4 = se[m + 4], e5 = se[m + 5], e6 = se[m + 6], e7 = se[m + 7];
                uint4 u0 = *(const uint4*)(xbase + e0.x);
                uint4 u1 = *(const uint4*)(xbase + e1.x);
                uint4 u2 = *(const uint4*)(xbase + e2.x);
                uint4 u3 = *(const uint4*)(xbase + e3.x);
                uint4 u4 = *(const uint4*)(xbase + e4.x);
                uint4 u5 = *(const uint4*)(xbase + e5.x);
                uint4 u6 = *(const uint4*)(xbase + e6.x);
                uint4 u7 = *(const uint4*)(xbase + e7.x);
                fma8(acc[il], __int_as_float(e0.y), u0);
                fma8(acc[il], __int_as_float(e1.y), u1);
                fma8(acc[il], __int_as_float(e2.y), u2);
                fma8(acc[il], __int_as_float(e3.y), u3);
                fma8(acc[il], __int_as_float(e4.y), u4);
                fma8(acc[il], __int_as_float(e5.y), u5);
                fma8(acc[il], __int_as_float(e6.y), u6);
                fma8(acc[il], __int_as_float(e7.y), u7);
            }
            for (; m + 4 <= me; m += 4) {
                int2 e0 = se[m], e1 = se[m + 1], e2 = se[m + 2], e3 = se[m + 3];
                uint4 u0 = *(const uint4*)(xbase + e0.x);
                uint4 u1 = *(const uint4*)(xbase + e1.x);
                uint4 u2 = *(const uint4*)(xbase + e2.x);
                uint4 u3 = *(const uint4*)(xbase + e3.x);
                fma8(acc[il], __int_as_float(e0.y), u0);
                fma8(acc[il], __int_as_float(e1.y), u1);
                fma8(acc[il], __int_as_float(e2.y), u2);
                fma8(acc[il], __int_as_float(e3.y), u3);
            }
            for (; m < me; m++) {
                int2 e = se[m];
                uint4 u = *(const uint4*)(xbase + e.x);
                fma8(acc[il], __int_as_float(e.y), u);
            }
        }
    }

    // Write 4 contiguous i-outputs (one float4) per owned n row
#pragma unroll
    for (int r = 0; r < 8; r++) {
        *(float4*)(out + (size_t)(n0 + r) * FDIM + i0) =
            make_float4(acc[0][r], acc[1][r], acc[2][r], acc[3][r]);
    }
}

// ---------------------------------------------------------------
extern "C" void kernel_launch(void* const* d_in, const int* in_sizes, int n_in,
                              void* d_out, int out_size) {
    const float* up_facts = (const float*)d_in[0];   // [NB, F]
    const float* down_enc = (const float*)d_in[1];   // [F, D]
    const float* up_dec   = (const float*)d_in[2];   // [D, F]
    const void*  ii       = d_in[3];                 // [M] sorted (int32 or int64)
    const void*  jj       = d_in[4];                 // [M]
    float* out = (float*)d_out;                      // [NB, F]

    k1_prep<<<K1_TOT, 256>>>(up_dec, up_facts, ii, jj);
    k2_fused<<<FDIM / ITILE, NTHR>>>(down_enc, out);
}